// round 13
// baseline (speedup 1.0000x reference)
#include <cuda_runtime.h>
#include <cstdint>

// Problem constants (fixed by the reference: B=8, S=1024, V=32000)
#define BB 8
#define SS 1024
#define VV 32000

#define NPROD 8               // producer slices per batch
#define PROD_F4 1000          // float4 per producer slice (NPROD*PROD_F4 == VV/4)
#define NTHREADS 1024

// Output layout (float32, concatenated flattened tuple in return order):
//   [0,              8192)   draft        [B, S]
//   [8192,           8200)   num_newly    [B]
//   [8200,           8208)   num_acc      [B]
//   [8208,           264208) last_logits  [B, 1, V]
#define OFF_DRAFT   0
#define OFF_NEWLY   (BB * SS)
#define OFF_ACC     (BB * SS + BB)
#define OFF_LASTLOG (BB * SS + 2 * BB)

#define IDX_SENTINEL 0x7fffffff

// Scratch (device globals: allocation-free). g_ctr is zero at module load and
// reset to zero by each finalizer before kernel exit -> deterministic replays.
__device__ unsigned int g_pval[BB][NPROD];
__device__ int          g_pidx[BB][NPROD];
__device__ unsigned int g_ctr[BB];

// Monotone (for non-NaN) float -> uint32 key: preserves float ordering.
__device__ __forceinline__ unsigned int f2ord(float f) {
    unsigned int u = __float_as_uint(f);
    return u ^ ((unsigned int)((int)u >> 31) | 0x80000000u);
}

// ---------------------------------------------------------------------------
// Fused kernel. grid = (NPROD+1, BB), block = 1024.
//   blockIdx.x < NPROD : producer (slice argmax of row npa-1 + lastlog copy)
//   blockIdx.x == NPROD: finalizer (combine, verify, epilogue; rare-chain walk)
// Deadlock-free: finalizers wait only on producers; producers wait on nothing;
// all 72 blocks fit in one co-resident wave (73728 thr << 148*2048).
// ---------------------------------------------------------------------------
__global__ __launch_bounds__(NTHREADS, 1)
void eagle_fused_kernel(const int* __restrict__ input_ids,
                        const float* __restrict__ target_logits,
                        const int* __restrict__ npa_arr,
                        float* __restrict__ out) {
    const int slice = blockIdx.x;
    const int b     = blockIdx.y;
    const int tid   = threadIdx.x;
    const int lane  = tid & 31;
    const int warp  = tid >> 5;

    const float* lg = target_logits + (size_t)b * SS * VV;
    float4* lastlog = (float4*)(out + OFF_LASTLOG + (size_t)b * VV);

    __shared__ unsigned int s_val[32];
    __shared__ int          s_idx[32];

    const float NEG_INF = __int_as_float(0xff800000);

    if (slice < NPROD) {
        // ================= PRODUCER =================
        const int npa = __ldg(&npa_arr[b]);
        const int row = npa - 1;

        const float4* src = (const float4*)(lg + (size_t)row * VV)
                            + slice * PROD_F4;
        float4* dst = lastlog + slice * PROD_F4;

        float bestf = NEG_INF;
        int   bidx  = IDX_SENTINEL;

        if (tid < PROD_F4) {
            float4 v = __ldcs(&src[tid]);
            __stcs(&dst[tid], v);      // speculative last_logits (finalizer
                                       // overwrites only in the rare case)
            int base = (slice * PROD_F4 + tid) << 2;
            if (v.x > bestf) { bestf = v.x; bidx = base;     }
            if (v.y > bestf) { bestf = v.y; bidx = base + 1; }
            if (v.z > bestf) { bestf = v.z; bidx = base + 2; }
            if (v.w > bestf) { bestf = v.w; bidx = base + 3; }
        }

        unsigned int ordv = f2ord(bestf);
        unsigned int wmax = __reduce_max_sync(0xffffffffu, ordv);
        int widx = __reduce_min_sync(0xffffffffu,
                                     (ordv == wmax) ? bidx : IDX_SENTINEL);
        if (lane == 0) { s_val[warp] = wmax; s_idx[warp] = widx; }
        __syncthreads();

        if (warp == 0) {
            unsigned int pv = s_val[lane];
            int          pi = s_idx[lane];
            unsigned int bmax = __reduce_max_sync(0xffffffffu, pv);
            int g = __reduce_min_sync(0xffffffffu,
                                      (pv == bmax) ? pi : IDX_SENTINEL);
            if (lane == 0) {
                g_pval[b][slice] = bmax;
                g_pidx[b][slice] = g;
                __threadfence();                 // release partials...
                atomicAdd(&g_ctr[b], 1u);        // ...then signal
            }
        }
        return;
    }

    // ================= FINALIZER =================
    const int* ids = input_ids + b * SS;

    // issue independent loads before the wait: they retire under the spin
    const int npa = __ldg(&npa_arr[b]);
    const int my_shifted_id = (tid < SS - 1) ? __ldg(&ids[tid + 1]) : 0;

    // lane 0 of warp 0 spins; everyone else parks at the barrier
    if (warp == 0 && lane == 0) {
        while (atomicAdd(&g_ctr[b], 0u) < NPROD) { }
    }
    __syncthreads();
    __threadfence();   // order partial reads after the observed signal

    // combine the NPROD partials (every warp redundantly; REDUX -> all lanes)
    unsigned int pv = (lane < NPROD) ? __ldcg(&g_pval[b][lane]) : 0u;
    int          pi = (lane < NPROD) ? __ldcg(&g_pidx[b][lane]) : IDX_SENTINEL;
    unsigned int bmax = __reduce_max_sync(0xffffffffu, pv);
    int greedy = __reduce_min_sync(0xffffffffu,
                                   (pv == bmax) ? pi : IDX_SENTINEL);

    // reset the counter for the next graph replay (after all partial reads)
    __syncthreads();
    if (tid == 0) g_ctr[b] = 0u;

    int k = npa - 1;
    int num_newly = 0;
    int bonus_tok;

    const int first_next = __ldg(&ids[npa]);   // npa <= 511 < SS, valid

    if (greedy != first_next) {
        // expected case (P ~ 1 - 1/32000): done, no logits traffic at all
        bonus_tok = greedy;
    } else {
        // rare: chain continues; walk rows npa, npa+1, ... with full block
        num_newly = 1;
        k = npa;
        bool first = true;

        for (;;) {
            if (!first) __syncthreads();
            first = false;

            const int next_id = (k < SS - 1) ? __ldg(&ids[k + 1]) : -1;

            const float4* row = (const float4*)(lg + (size_t)k * VV);
            float bestf = NEG_INF;
            int   bidx  = IDX_SENTINEL;

            #pragma unroll 8
            for (int i = tid; i < VV / 4; i += NTHREADS) {
                float4 v = __ldcs(&row[i]);
                __stcs(&lastlog[i], v);    // overwrite speculative copy
                int base = i << 2;
                if (v.x > bestf) { bestf = v.x; bidx = base;     }
                if (v.y > bestf) { bestf = v.y; bidx = base + 1; }
                if (v.z > bestf) { bestf = v.z; bidx = base + 2; }
                if (v.w > bestf) { bestf = v.w; bidx = base + 3; }
            }

            unsigned int ordv = f2ord(bestf);
            unsigned int wmax = __reduce_max_sync(0xffffffffu, ordv);
            int widx = __reduce_min_sync(0xffffffffu,
                                         (ordv == wmax) ? bidx : IDX_SENTINEL);
            if (lane == 0) { s_val[warp] = wmax; s_idx[warp] = widx; }
            __syncthreads();

            unsigned int qv = s_val[lane];
            int          qi = s_idx[lane];
            unsigned int qmax = __reduce_max_sync(0xffffffffu, qv);
            const int g = __reduce_min_sync(0xffffffffu,
                                            (qv == qmax) ? qi : IDX_SENTINEL);

            if (g == next_id) {
                num_newly++;
                k++;
            } else {
                bonus_tok = g;
                break;
            }
        }
    }

    const int num_acc = npa + num_newly;

    // ---- draft tokens: one element per thread (S == NTHREADS) ----
    {
        const int t = tid;
        float val;
        if (t < num_acc - 1)       val = (float)my_shifted_id;
        else if (t == num_acc - 1) val = (float)bonus_tok;
        else                       val = 0.0f;
        out[OFF_DRAFT + b * SS + t] = val;
    }

    // ---- scalars ----
    if (tid == 0) {
        out[OFF_NEWLY + b] = (float)num_newly;
        out[OFF_ACC   + b] = (float)num_acc;
    }
}

extern "C" void kernel_launch(void* const* d_in, const int* in_sizes, int n_in,
                              void* d_out, int out_size) {
    const int*   input_ids     = (const int*)d_in[0];
    const float* target_logits = (const float*)d_in[1];
    const int*   npa           = (const int*)d_in[2];
    float* out = (float*)d_out;

    dim3 grid(NPROD + 1, BB);
    eagle_fused_kernel<<<grid, NTHREADS>>>(input_ids, target_logits, npa, out);
}